// round 1
// baseline (speedup 1.0000x reference)
#include <cuda_runtime.h>
#include <math.h>
#include <stdint.h>

#define B_ 4
#define N_ 2048
#define IN_F 512
#define OUT_F 512
#define INTERNAL 256
#define REL_DIM 10
#define NUM_REL 6
#define ALPHA_ 0.2f
#define NEG_INF_ -9000000000000000.0f
#define EPS_LN_ 1e-5f

// LAMBDA_INIT = 0.8 - 0.6*exp(-0.3) computed in double
#define LAMBDA_INIT_ 0.35550906759096927f
#define ONE_MINUS_LAMBDA_ 0.64449093240903073f

// ---------------------------------------------------------------------------
// Device scratch (no allocations allowed in kernel_launch)
// ---------------------------------------------------------------------------
__device__ __align__(128) float g_Wh[(size_t)B_ * N_ * OUT_F];        // 16 MB
__device__ __align__(128) float g_hprime[(size_t)B_ * N_ * OUT_F];    // 16 MB
__device__ __align__(128) float g_att_fallback[(size_t)B_ * N_ * N_]; // 64 MB (only if d_out lacks attention)
__device__ float g_lpos[B_ * N_];
__device__ float g_rpos[B_ * N_];
__device__ float g_lneg[B_ * N_];
__device__ float g_rneg[B_ * N_];
__device__ float g_relp[NUM_REL];
__device__ float g_reln[NUM_REL];
__device__ float g_lam;

// ---------------------------------------------------------------------------
// Tiny prep kernel: lambda scalar + rel-table LUT (6 entries each)
// ---------------------------------------------------------------------------
__global__ void prep_kernel(const float* __restrict__ ll1, const float* __restrict__ lr1,
                            const float* __restrict__ ll2, const float* __restrict__ lr2,
                            const float* __restrict__ rel_table,
                            const float* __restrict__ a_rel_pos,
                            const float* __restrict__ a_rel_neg) {
    __shared__ float s1[256];
    __shared__ float s2[256];
    int t = threadIdx.x;
    s1[t] = ll1[t] * lr1[t];
    s2[t] = ll2[t] * lr2[t];
    __syncthreads();
    for (int s = 128; s > 0; s >>= 1) {
        if (t < s) { s1[t] += s1[t + s]; s2[t] += s2[t + s]; }
        __syncthreads();
    }
    if (t == 0) g_lam = expf(s1[0]) - expf(s2[0]) + LAMBDA_INIT_;
    if (t < NUM_REL) {
        float sp = 0.f, sn = 0.f;
        #pragma unroll
        for (int d = 0; d < REL_DIM; d++) {
            float r = rel_table[t * REL_DIM + d];
            sp += r * a_rel_pos[d];
            sn += r * a_rel_neg[d];
        }
        g_relp[t] = sp;
        g_reln[t] = sn;
    }
}

// ---------------------------------------------------------------------------
// Classic 128x128x8 SGEMM, 256 threads, 8x8 micro-tile.
// A row-major [M,K], B row-major [K,N], C row-major [M,N].
// All dims divisible by tile sizes for this problem (no bounds checks).
// blockIdx.z = batch; strides in elements.
// ---------------------------------------------------------------------------
#define BM 128
#define BN 128
#define BKK 8
#define TM 8
#define TN 8

__global__ __launch_bounds__(256, 2) void sgemm_kernel(
    const float* __restrict__ A, const float* __restrict__ B, float* __restrict__ C,
    int M, int N, int K,
    size_t strideA, size_t strideB, size_t strideC) {
    int b = blockIdx.z;
    A += (size_t)b * strideA;
    B += (size_t)b * strideB;
    C += (size_t)b * strideC;

    const int cRow = blockIdx.y;
    const int cCol = blockIdx.x;

    __shared__ float As[BKK][BM];
    __shared__ float Bs[BKK][BN];

    const int tid = threadIdx.x;
    const int threadCol = tid % (BN / TN);  // 0..15
    const int threadRow = tid / (BN / TN);  // 0..15

    const int innerRowA = tid >> 1;          // 0..127
    const int innerColA = (tid & 1) * 4;     // 0 or 4
    const int innerRowB = tid >> 5;          // 0..7
    const int innerColB = (tid & 31) * 4;    // 0..124

    float acc[TM][TN];
    #pragma unroll
    for (int i = 0; i < TM; i++)
        #pragma unroll
        for (int j = 0; j < TN; j++) acc[i][j] = 0.f;

    float regM[TM], regN[TN];

    const float* Aptr = A + (size_t)(cRow * BM) * K;
    const float* Bptr = B + cCol * BN;

    for (int k0 = 0; k0 < K; k0 += BKK) {
        float4 a4 = *reinterpret_cast<const float4*>(Aptr + (size_t)innerRowA * K + k0 + innerColA);
        As[innerColA + 0][innerRowA] = a4.x;
        As[innerColA + 1][innerRowA] = a4.y;
        As[innerColA + 2][innerRowA] = a4.z;
        As[innerColA + 3][innerRowA] = a4.w;
        float4 b4 = *reinterpret_cast<const float4*>(Bptr + (size_t)(k0 + innerRowB) * N + innerColB);
        *reinterpret_cast<float4*>(&Bs[innerRowB][innerColB]) = b4;
        __syncthreads();

        #pragma unroll
        for (int k = 0; k < BKK; ++k) {
            #pragma unroll
            for (int i = 0; i < TM; i++) regM[i] = As[k][threadRow * TM + i];
            #pragma unroll
            for (int j = 0; j < TN; j++) regN[j] = Bs[k][threadCol * TN + j];
            #pragma unroll
            for (int i = 0; i < TM; i++)
                #pragma unroll
                for (int j = 0; j < TN; j++) acc[i][j] += regM[i] * regN[j];
        }
        __syncthreads();
    }

    #pragma unroll
    for (int i = 0; i < TM; i++) {
        size_t row = (size_t)(cRow * BM + threadRow * TM + i);
        float* crow = C + row * N + cCol * BN + threadCol * TN;
        #pragma unroll
        for (int j = 0; j < TN; j += 4) {
            float4 v = make_float4(acc[i][j], acc[i][j + 1], acc[i][j + 2], acc[i][j + 3]);
            *reinterpret_cast<float4*>(crow + j) = v;
        }
    }
}

// ---------------------------------------------------------------------------
// Per-row dots: l/r scores for pos/neg halves of Wh
// ---------------------------------------------------------------------------
__global__ void rowdots_kernel(const float* __restrict__ alp, const float* __restrict__ arp,
                               const float* __restrict__ aln, const float* __restrict__ arn) {
    int row = blockIdx.x;
    int t = threadIdx.x;
    const float* wh = g_Wh + (size_t)row * OUT_F;
    float whp = wh[t];
    float whn = wh[INTERNAL + t];
    __shared__ float s[4][256];
    s[0][t] = whp * alp[t];
    s[1][t] = whp * arp[t];
    s[2][t] = whn * aln[t];
    s[3][t] = whn * arn[t];
    __syncthreads();
    for (int st = 128; st > 0; st >>= 1) {
        if (t < st) {
            s[0][t] += s[0][t + st];
            s[1][t] += s[1][t + st];
            s[2][t] += s[2][t + st];
            s[3][t] += s[3][t + st];
        }
        __syncthreads();
    }
    if (t == 0) {
        g_lpos[row] = s[0][0];
        g_rpos[row] = s[1][0];
        g_lneg[row] = s[2][0];
        g_rneg[row] = s[3][0];
    }
}

// ---------------------------------------------------------------------------
// Attention: one block per (b,i) row. Dual masked softmax over j, combine.
// ---------------------------------------------------------------------------
__global__ __launch_bounds__(256) void attention_kernel(const int* __restrict__ adj,
                                                        float* __restrict__ att_out) {
    int row = blockIdx.x;  // b*N + i
    int b = row / N_;
    const int* arow = adj + (size_t)row * N_;
    const float* rp = g_rpos + b * N_;
    const float* rn = g_rneg + b * N_;
    float lp = g_lpos[row];
    float ln_ = g_lneg[row];
    float lam = g_lam;

    __shared__ float s_ep[N_];
    __shared__ float s_en[N_];
    __shared__ float red[256];
    int t = threadIdx.x;

    float mp = -INFINITY, mn = -INFINITY;
    for (int j = t; j < N_; j += 256) {
        int a = arow[j];
        float ep, en;
        if (a > 0) {
            float x = lp + rp[j] + g_relp[a];
            ep = (x >= 0.f) ? x : ALPHA_ * x;
            float y = ln_ + rn[j] + g_reln[a];
            en = (y >= 0.f) ? y : ALPHA_ * y;
        } else {
            ep = NEG_INF_;
            en = NEG_INF_;
        }
        s_ep[j] = ep;
        s_en[j] = en;
        mp = fmaxf(mp, ep);
        mn = fmaxf(mn, en);
    }
    red[t] = mp; __syncthreads();
    for (int s = 128; s > 0; s >>= 1) { if (t < s) red[t] = fmaxf(red[t], red[t + s]); __syncthreads(); }
    mp = red[0]; __syncthreads();
    red[t] = mn; __syncthreads();
    for (int s = 128; s > 0; s >>= 1) { if (t < s) red[t] = fmaxf(red[t], red[t + s]); __syncthreads(); }
    mn = red[0]; __syncthreads();

    float sp = 0.f, sn = 0.f;
    for (int j = t; j < N_; j += 256) {
        float p = expf(s_ep[j] - mp);
        float q = expf(s_en[j] - mn);
        s_ep[j] = p;
        s_en[j] = q;
        sp += p;
        sn += q;
    }
    red[t] = sp; __syncthreads();
    for (int s = 128; s > 0; s >>= 1) { if (t < s) red[t] += red[t + s]; __syncthreads(); }
    sp = red[0]; __syncthreads();
    red[t] = sn; __syncthreads();
    for (int s = 128; s > 0; s >>= 1) { if (t < s) red[t] += red[t + s]; __syncthreads(); }
    sn = red[0];

    float isp = 1.0f / sp;
    float isn = lam / sn;
    float* orow = att_out + (size_t)row * N_;
    for (int j = t; j < N_; j += 256) {
        orow[j] = s_ep[j] * isp - s_en[j] * isn;
    }
}

// ---------------------------------------------------------------------------
// LayerNorm + scale + exact GELU epilogue. One block per row (512 elems).
// ---------------------------------------------------------------------------
__global__ void ln_gelu_kernel(const float* __restrict__ gamma, const float* __restrict__ beta,
                               float* __restrict__ out) {
    int row = blockIdx.x;
    int t = threadIdx.x;
    const float* x = g_hprime + (size_t)row * OUT_F;
    float x0 = x[t];
    float x1 = x[t + 256];
    __shared__ float red[256];
    red[t] = x0 + x1; __syncthreads();
    for (int s = 128; s > 0; s >>= 1) { if (t < s) red[t] += red[t + s]; __syncthreads(); }
    float mu = red[0] * (1.0f / OUT_F);
    __syncthreads();
    float d0 = x0 - mu, d1 = x1 - mu;
    red[t] = d0 * d0 + d1 * d1; __syncthreads();
    for (int s = 128; s > 0; s >>= 1) { if (t < s) red[t] += red[t + s]; __syncthreads(); }
    float var = red[0] * (1.0f / OUT_F);
    float inv = rsqrtf(var + EPS_LN_);

    float y0 = (d0 * inv * gamma[t] + beta[t]) * ONE_MINUS_LAMBDA_;
    float y1 = (d1 * inv * gamma[t + 256] + beta[t + 256]) * ONE_MINUS_LAMBDA_;
    float* o = out + (size_t)row * OUT_F;
    o[t]       = y0 * 0.5f * (1.0f + erff(y0 * 0.7071067811865476f));
    o[t + 256] = y1 * 0.5f * (1.0f + erff(y1 * 0.7071067811865476f));
}

// ---------------------------------------------------------------------------
// Launch
// ---------------------------------------------------------------------------
extern "C" void kernel_launch(void* const* d_in, const int* in_sizes, int n_in,
                              void* d_out, int out_size) {
    const float* h         = (const float*)d_in[0];
    const int*   adj       = (const int*)d_in[1];
    const float* W         = (const float*)d_in[2];
    const float* alp       = (const float*)d_in[3];
    const float* arp       = (const float*)d_in[4];
    const float* aln       = (const float*)d_in[5];
    const float* arn       = (const float*)d_in[6];
    const float* rel_table = (const float*)d_in[7];
    const float* a_rel_pos = (const float*)d_in[8];
    const float* a_rel_neg = (const float*)d_in[9];
    const float* ll1       = (const float*)d_in[10];
    const float* lr1       = (const float*)d_in[11];
    const float* ll2       = (const float*)d_in[12];
    const float* lr2       = (const float*)d_in[13];
    const float* gamma     = (const float*)d_in[14];
    const float* beta      = (const float*)d_in[15];
    float* out = (float*)d_out;

    const size_t GE = (size_t)B_ * N_ * OUT_F;       // gelu output elems
    const size_t AT = (size_t)B_ * N_ * N_;          // attention output elems

    float* att_out;
    if ((size_t)out_size >= GE + AT) {
        att_out = out + GE;                           // tuple layout: [gelu | attention]
    } else {
        void* p;
        cudaGetSymbolAddress(&p, g_att_fallback);     // attention not part of checked output
        att_out = (float*)p;
    }

    void* pWh_v;  cudaGetSymbolAddress(&pWh_v, g_Wh);
    void* pHp_v;  cudaGetSymbolAddress(&pHp_v, g_hprime);
    float* pWh = (float*)pWh_v;
    float* pHp = (float*)pHp_v;

    // 1) scalars + rel LUT
    prep_kernel<<<1, 256>>>(ll1, lr1, ll2, lr2, rel_table, a_rel_pos, a_rel_neg);

    // 2) Wh = h @ W   (M=8192, N=512, K=512; batch folded into M)
    {
        dim3 grid(OUT_F / BN, (B_ * N_) / BM, 1);
        sgemm_kernel<<<grid, 256>>>(h, W, pWh, B_ * N_, OUT_F, IN_F, 0, 0, 0);
    }

    // 3) per-row left/right scores
    rowdots_kernel<<<B_ * N_, 256>>>(alp, arp, aln, arn);

    // 4) attention rows (dual masked softmax, combined)
    attention_kernel<<<B_ * N_, 256>>>(adj, att_out);

    // 5) h_prime = attention @ Wh   (per batch: M=2048, N=512, K=2048)
    {
        dim3 grid(OUT_F / BN, N_ / BM, B_);
        sgemm_kernel<<<grid, 256>>>(att_out, pWh, pHp, N_, OUT_F, N_,
                                    (size_t)N_ * N_, (size_t)N_ * OUT_F, (size_t)N_ * OUT_F);
    }

    // 6) LayerNorm + scale + exact GELU -> first output region
    ln_gelu_kernel<<<B_ * N_, 256>>>(gamma, beta, out);
}

// round 3
// speedup vs baseline: 1.5624x; 1.5624x over previous
#include <cuda_runtime.h>
#include <cuda_bf16.h>
#include <mma.h>
#include <math.h>
#include <stdint.h>

using namespace nvcuda;

#define B_ 4
#define N_ 2048
#define IN_F 512
#define OUT_F 512
#define INTERNAL 256
#define REL_DIM 10
#define NUM_REL 6
#define ALPHA_ 0.2f
#define NEG_INF_ -9000000000000000.0f
#define EPS_LN_ 1e-5f

#define LAMBDA_INIT_ 0.35550906759096927f
#define ONE_MINUS_LAMBDA_ 0.64449093240903073f

// ---------------------------------------------------------------------------
// Device scratch
// ---------------------------------------------------------------------------
__device__ __align__(128) float g_Wh[(size_t)B_ * N_ * OUT_F];         // 16 MB
__device__ __align__(128) float g_hprime[(size_t)B_ * N_ * OUT_F];     // 16 MB
__device__ __align__(128) float g_att_fallback[(size_t)B_ * N_ * N_];  // 64 MB
__device__ float g_lpos[B_ * N_];
__device__ float g_rpos[B_ * N_];
__device__ float g_lneg[B_ * N_];
__device__ float g_rneg[B_ * N_];
__device__ float g_relp[NUM_REL];
__device__ float g_reln[NUM_REL];
__device__ float g_lam;

// ---------------------------------------------------------------------------
// Prep: lambda scalar + rel LUT
// ---------------------------------------------------------------------------
__global__ void prep_kernel(const float* __restrict__ ll1, const float* __restrict__ lr1,
                            const float* __restrict__ ll2, const float* __restrict__ lr2,
                            const float* __restrict__ rel_table,
                            const float* __restrict__ a_rel_pos,
                            const float* __restrict__ a_rel_neg) {
    __shared__ float s1[256];
    __shared__ float s2[256];
    int t = threadIdx.x;
    s1[t] = ll1[t] * lr1[t];
    s2[t] = ll2[t] * lr2[t];
    __syncthreads();
    for (int s = 128; s > 0; s >>= 1) {
        if (t < s) { s1[t] += s1[t + s]; s2[t] += s2[t + s]; }
        __syncthreads();
    }
    if (t == 0) g_lam = expf(s1[0]) - expf(s2[0]) + LAMBDA_INIT_;
    if (t < NUM_REL) {
        float sp = 0.f, sn = 0.f;
        #pragma unroll
        for (int d = 0; d < REL_DIM; d++) {
            float r = rel_table[t * REL_DIM + d];
            sp += r * a_rel_pos[d];
            sn += r * a_rel_neg[d];
        }
        g_relp[t] = sp;
        g_reln[t] = sn;
    }
}

// ---------------------------------------------------------------------------
// WMMA bf16 3x-split GEMM.
//   C[M,N] = A[M,K] @ B[K,N], both fp32 row-major in gmem, split to bf16
//   hi/lo on the fly into SMEM. C = Ah*Bh + Ah*Bl + Al*Bh (fp32 accum).
// CTA tile 128x128, BK=32, 256 threads = 8 warps (4 in M x 2 in N),
// warp tile 32x64 = 2x4 fragments of 16x16x16. Double-buffered SMEM.
// grid: (N/128, M/128, batch)
// ---------------------------------------------------------------------------
#define BM 128
#define BN 128
#define BK 32
#define LDA 40    // bf16 elems per A smem row (32 + 8 pad)
#define LDB 136   // bf16 elems per B smem row (128 + 8 pad)

#define A_TILE_ELEMS (BM * LDA)              // 5120 bf16
#define B_TILE_ELEMS (BK * LDB)              // 4352 bf16
#define STAGE_ELEMS (2 * A_TILE_ELEMS + 2 * B_TILE_ELEMS)  // ah, al, bh, bl
#define GEMM_SMEM_BYTES (2 * STAGE_ELEMS * 2)

extern __shared__ __nv_bfloat16 g_smem_bf[];

__global__ __launch_bounds__(256) void gemm_wmma_kernel(
    const float* __restrict__ A, const float* __restrict__ B, float* __restrict__ C,
    int K, int NN,
    size_t sA, size_t sB, size_t sC) {
    const int tid = threadIdx.x;
    const int wid = tid >> 5;
    const int wm = wid & 3;        // 0..3 (M)
    const int wn = wid >> 2;       // 0..1 (N)

    const int n0 = blockIdx.x * BN;
    const int m0 = blockIdx.y * BM;
    const int bz = blockIdx.z;

    const float* Ag = A + (size_t)bz * sA + (size_t)m0 * K;
    const float* Bg = B + (size_t)bz * sB;
    float*       Cg = C + (size_t)bz * sC;

    // per-thread gmem load coordinates
    const int ar = tid >> 3;           // A: row (tid..) -> rows 0..127 via +32*i
    const int ac4 = (tid & 7) * 4;     // A: col (float)
    const int br = tid >> 5;           // B: row 0..7 via +8*i
    const int bc4 = (tid & 31) * 4;    // B: col

    wmma::fragment<wmma::accumulator, 16, 16, 16, float> acc[2][4];
    #pragma unroll
    for (int i = 0; i < 2; i++)
        #pragma unroll
        for (int j = 0; j < 4; j++) wmma::fill_fragment(acc[i][j], 0.0f);

    const int nt = K / BK;
    float4 av[4], bv[4];

    // prefetch tile 0
    {
        #pragma unroll
        for (int i = 0; i < 4; i++) {
            av[i] = *reinterpret_cast<const float4*>(Ag + (size_t)(ar + 32 * i) * K + ac4);
            bv[i] = *reinterpret_cast<const float4*>(Bg + (size_t)(br + 8 * i) * NN + n0 + bc4);
        }
    }

    for (int t = 0; t < nt; t++) {
        const int p = t & 1;
        __nv_bfloat16* sa_hi = g_smem_bf + p * STAGE_ELEMS;
        __nv_bfloat16* sa_lo = sa_hi + A_TILE_ELEMS;
        __nv_bfloat16* sb_hi = sa_lo + A_TILE_ELEMS;
        __nv_bfloat16* sb_lo = sb_hi + B_TILE_ELEMS;

        // store prefetched regs to smem, splitting hi/lo
        #pragma unroll
        for (int i = 0; i < 4; i++) {
            const float* v = reinterpret_cast<const float*>(&av[i]);
            __nv_bfloat16 h0 = __float2bfloat16_rn(v[0]);
            __nv_bfloat16 h1 = __float2bfloat16_rn(v[1]);
            __nv_bfloat16 h2 = __float2bfloat16_rn(v[2]);
            __nv_bfloat16 h3 = __float2bfloat16_rn(v[3]);
            __nv_bfloat16 l0 = __float2bfloat16_rn(v[0] - __bfloat162float(h0));
            __nv_bfloat16 l1 = __float2bfloat16_rn(v[1] - __bfloat162float(h1));
            __nv_bfloat16 l2 = __float2bfloat16_rn(v[2] - __bfloat162float(h2));
            __nv_bfloat16 l3 = __float2bfloat16_rn(v[3] - __bfloat162float(h3));
            int off = (ar + 32 * i) * LDA + ac4;
            *reinterpret_cast<__nv_bfloat162*>(sa_hi + off)     = __nv_bfloat162(h0, h1);
            *reinterpret_cast<__nv_bfloat162*>(sa_hi + off + 2) = __nv_bfloat162(h2, h3);
            *reinterpret_cast<__nv_bfloat162*>(sa_lo + off)     = __nv_bfloat162(l0, l1);
            *reinterpret_cast<__nv_bfloat162*>(sa_lo + off + 2) = __nv_bfloat162(l2, l3);
        }
        #pragma unroll
        for (int i = 0; i < 4; i++) {
            const float* v = reinterpret_cast<const float*>(&bv[i]);
            __nv_bfloat16 h0 = __float2bfloat16_rn(v[0]);
            __nv_bfloat16 h1 = __float2bfloat16_rn(v[1]);
            __nv_bfloat16 h2 = __float2bfloat16_rn(v[2]);
            __nv_bfloat16 h3 = __float2bfloat16_rn(v[3]);
            __nv_bfloat16 l0 = __float2bfloat16_rn(v[0] - __bfloat162float(h0));
            __nv_bfloat16 l1 = __float2bfloat16_rn(v[1] - __bfloat162float(h1));
            __nv_bfloat16 l2 = __float2bfloat16_rn(v[2] - __bfloat162float(h2));
            __nv_bfloat16 l3 = __float2bfloat16_rn(v[3] - __bfloat162float(h3));
            int off = (br + 8 * i) * LDB + bc4;
            *reinterpret_cast<__nv_bfloat162*>(sb_hi + off)     = __nv_bfloat162(h0, h1);
            *reinterpret_cast<__nv_bfloat162*>(sb_hi + off + 2) = __nv_bfloat162(h2, h3);
            *reinterpret_cast<__nv_bfloat162*>(sb_lo + off)     = __nv_bfloat162(l0, l1);
            *reinterpret_cast<__nv_bfloat162*>(sb_lo + off + 2) = __nv_bfloat162(l2, l3);
        }
        __syncthreads();

        // prefetch next tile
        if (t + 1 < nt) {
            const int k0 = (t + 1) * BK;
            #pragma unroll
            for (int i = 0; i < 4; i++) {
                av[i] = *reinterpret_cast<const float4*>(Ag + (size_t)(ar + 32 * i) * K + k0 + ac4);
                bv[i] = *reinterpret_cast<const float4*>(Bg + (size_t)(k0 + br + 8 * i) * NN + n0 + bc4);
            }
        }

        // compute on current stage
        #pragma unroll
        for (int kk = 0; kk < BK; kk += 16) {
            wmma::fragment<wmma::matrix_a, 16, 16, 16, __nv_bfloat16, wmma::row_major> ah[2], al[2];
            wmma::fragment<wmma::matrix_b, 16, 16, 16, __nv_bfloat16, wmma::row_major> bh[4], bl[4];
            #pragma unroll
            for (int i = 0; i < 2; i++) {
                int row = wm * 32 + i * 16;
                wmma::load_matrix_sync(ah[i], sa_hi + row * LDA + kk, LDA);
                wmma::load_matrix_sync(al[i], sa_lo + row * LDA + kk, LDA);
            }
            #pragma unroll
            for (int j = 0; j < 4; j++) {
                int col = wn * 64 + j * 16;
                wmma::load_matrix_sync(bh[j], sb_hi + kk * LDB + col, LDB);
                wmma::load_matrix_sync(bl[j], sb_lo + kk * LDB + col, LDB);
            }
            #pragma unroll
            for (int i = 0; i < 2; i++)
                #pragma unroll
                for (int j = 0; j < 4; j++) {
                    wmma::mma_sync(acc[i][j], ah[i], bh[j], acc[i][j]);
                    wmma::mma_sync(acc[i][j], ah[i], bl[j], acc[i][j]);
                    wmma::mma_sync(acc[i][j], al[i], bh[j], acc[i][j]);
                }
        }
        __syncthreads();
    }

    // epilogue
    #pragma unroll
    for (int i = 0; i < 2; i++) {
        int row = m0 + wm * 32 + i * 16;
        #pragma unroll
        for (int j = 0; j < 4; j++) {
            int col = n0 + wn * 64 + j * 16;
            wmma::store_matrix_sync(Cg + (size_t)row * NN + col, acc[i][j], NN,
                                    wmma::mem_row_major);
        }
    }
}

// ---------------------------------------------------------------------------
// Per-row dots
// ---------------------------------------------------------------------------
__global__ void rowdots_kernel(const float* __restrict__ alp, const float* __restrict__ arp,
                               const float* __restrict__ aln, const float* __restrict__ arn) {
    int row = blockIdx.x;
    int t = threadIdx.x;
    const float* wh = g_Wh + (size_t)row * OUT_F;
    float whp = wh[t];
    float whn = wh[INTERNAL + t];
    __shared__ float s[4][256];
    s[0][t] = whp * alp[t];
    s[1][t] = whp * arp[t];
    s[2][t] = whn * aln[t];
    s[3][t] = whn * arn[t];
    __syncthreads();
    for (int st = 128; st > 0; st >>= 1) {
        if (t < st) {
            s[0][t] += s[0][t + st];
            s[1][t] += s[1][t + st];
            s[2][t] += s[2][t + st];
            s[3][t] += s[3][t + st];
        }
        __syncthreads();
    }
    if (t == 0) {
        g_lpos[row] = s[0][0];
        g_rpos[row] = s[1][0];
        g_lneg[row] = s[2][0];
        g_rneg[row] = s[3][0];
    }
}

// ---------------------------------------------------------------------------
// Attention rows: dual masked softmax + combine
// ---------------------------------------------------------------------------
__global__ __launch_bounds__(256) void attention_kernel(const int* __restrict__ adj,
                                                        float* __restrict__ att_out) {
    int row = blockIdx.x;
    int b = row / N_;
    const int* arow = adj + (size_t)row * N_;
    const float* rp = g_rpos + b * N_;
    const float* rn = g_rneg + b * N_;
    float lp = g_lpos[row];
    float ln_ = g_lneg[row];
    float lam = g_lam;

    __shared__ float s_ep[N_];
    __shared__ float s_en[N_];
    __shared__ float red[256];
    int t = threadIdx.x;

    float mp = -INFINITY, mn = -INFINITY;
    for (int j = t; j < N_; j += 256) {
        int a = arow[j];
        float ep, en;
        if (a > 0) {
            float x = lp + rp[j] + g_relp[a];
            ep = (x >= 0.f) ? x : ALPHA_ * x;
            float y = ln_ + rn[j] + g_reln[a];
            en = (y >= 0.f) ? y : ALPHA_ * y;
        } else {
            ep = NEG_INF_;
            en = NEG_INF_;
        }
        s_ep[j] = ep;
        s_en[j] = en;
        mp = fmaxf(mp, ep);
        mn = fmaxf(mn, en);
    }
    red[t] = mp; __syncthreads();
    for (int s = 128; s > 0; s >>= 1) { if (t < s) red[t] = fmaxf(red[t], red[t + s]); __syncthreads(); }
    mp = red[0]; __syncthreads();
    red[t] = mn; __syncthreads();
    for (int s = 128; s > 0; s >>= 1) { if (t < s) red[t] = fmaxf(red[t], red[t + s]); __syncthreads(); }
    mn = red[0]; __syncthreads();

    float sp = 0.f, sn = 0.f;
    for (int j = t; j < N_; j += 256) {
        float p = __expf(s_ep[j] - mp);
        float q = __expf(s_en[j] - mn);
        s_ep[j] = p;
        s_en[j] = q;
        sp += p;
        sn += q;
    }
    red[t] = sp; __syncthreads();
    for (int s = 128; s > 0; s >>= 1) { if (t < s) red[t] += red[t + s]; __syncthreads(); }
    sp = red[0]; __syncthreads();
    red[t] = sn; __syncthreads();
    for (int s = 128; s > 0; s >>= 1) { if (t < s) red[t] += red[t + s]; __syncthreads(); }
    sn = red[0];

    float isp = 1.0f / sp;
    float isn = lam / sn;
    float* orow = att_out + (size_t)row * N_;
    for (int j = t; j < N_; j += 256) {
        orow[j] = s_ep[j] * isp - s_en[j] * isn;
    }
}

// ---------------------------------------------------------------------------
// LayerNorm + scale + exact GELU
// ---------------------------------------------------------------------------
__global__ void ln_gelu_kernel(const float* __restrict__ gamma, const float* __restrict__ beta,
                               float* __restrict__ out) {
    int row = blockIdx.x;
    int t = threadIdx.x;
    const float* x = g_hprime + (size_t)row * OUT_F;
    float x0 = x[t];
    float x1 = x[t + 256];
    __shared__ float red[256];
    red[t] = x0 + x1; __syncthreads();
    for (int s = 128; s > 0; s >>= 1) { if (t < s) red[t] += red[t + s]; __syncthreads(); }
    float mu = red[0] * (1.0f / OUT_F);
    __syncthreads();
    float d0 = x0 - mu, d1 = x1 - mu;
    red[t] = d0 * d0 + d1 * d1; __syncthreads();
    for (int s = 128; s > 0; s >>= 1) { if (t < s) red[t] += red[t + s]; __syncthreads(); }
    float var = red[0] * (1.0f / OUT_F);
    float inv = rsqrtf(var + EPS_LN_);

    float y0 = (d0 * inv * gamma[t] + beta[t]) * ONE_MINUS_LAMBDA_;
    float y1 = (d1 * inv * gamma[t + 256] + beta[t + 256]) * ONE_MINUS_LAMBDA_;
    float* o = out + (size_t)row * OUT_F;
    o[t]       = y0 * 0.5f * (1.0f + erff(y0 * 0.7071067811865476f));
    o[t + 256] = y1 * 0.5f * (1.0f + erff(y1 * 0.7071067811865476f));
}

// ---------------------------------------------------------------------------
// Launch
// ---------------------------------------------------------------------------
extern "C" void kernel_launch(void* const* d_in, const int* in_sizes, int n_in,
                              void* d_out, int out_size) {
    const float* h         = (const float*)d_in[0];
    const int*   adj       = (const int*)d_in[1];
    const float* W         = (const float*)d_in[2];
    const float* alp       = (const float*)d_in[3];
    const float* arp       = (const float*)d_in[4];
    const float* aln       = (const float*)d_in[5];
    const float* arn       = (const float*)d_in[6];
    const float* rel_table = (const float*)d_in[7];
    const float* a_rel_pos = (const float*)d_in[8];
    const float* a_rel_neg = (const float*)d_in[9];
    const float* ll1       = (const float*)d_in[10];
    const float* lr1       = (const float*)d_in[11];
    const float* ll2       = (const float*)d_in[12];
    const float* lr2       = (const float*)d_in[13];
    const float* gamma     = (const float*)d_in[14];
    const float* beta      = (const float*)d_in[15];
    float* out = (float*)d_out;

    const size_t GE = (size_t)B_ * N_ * OUT_F;
    const size_t AT = (size_t)B_ * N_ * N_;

    float* att_out;
    if ((size_t)out_size >= GE + AT) {
        att_out = out + GE;
    } else {
        void* p;
        cudaGetSymbolAddress(&p, g_att_fallback);
        att_out = (float*)p;
    }

    void *pWh, *pHp;
    cudaGetSymbolAddress(&pWh, g_Wh);
    cudaGetSymbolAddress(&pHp, g_hprime);

    cudaFuncSetAttribute(gemm_wmma_kernel, cudaFuncAttributeMaxDynamicSharedMemorySize,
                         GEMM_SMEM_BYTES);

    // 1) scalars + rel LUT
    prep_kernel<<<1, 256>>>(ll1, lr1, ll2, lr2, rel_table, a_rel_pos, a_rel_neg);

    // 2) Wh = h @ W   (M=8192, N=512, K=512)
    {
        dim3 grid(OUT_F / BN, (B_ * N_) / BM, 1);
        gemm_wmma_kernel<<<grid, 256, GEMM_SMEM_BYTES>>>(h, W, (float*)pWh, IN_F, OUT_F, 0, 0, 0);
    }

    // 3) per-row scores
    rowdots_kernel<<<B_ * N_, 256>>>(alp, arp, aln, arn);

    // 4) attention rows
    attention_kernel<<<B_ * N_, 256>>>(adj, att_out);

    // 5) h_prime = attention @ Wh   (per batch M=2048, N=512, K=2048)
    {
        dim3 grid(OUT_F / BN, N_ / BM, B_);
        gemm_wmma_kernel<<<grid, 256, GEMM_SMEM_BYTES>>>(att_out, (const float*)pWh, (float*)pHp,
                                                         N_, OUT_F,
                                                         (size_t)N_ * N_, (size_t)N_ * OUT_F,
                                                         (size_t)N_ * OUT_F);
    }

    // 6) LN + GELU
    ln_gelu_kernel<<<B_ * N_, 256>>>(gamma, beta, out);
}

// round 4
// speedup vs baseline: 2.0581x; 1.3172x over previous
#include <cuda_runtime.h>
#include <cuda_bf16.h>
#include <mma.h>
#include <math.h>
#include <stdint.h>

using namespace nvcuda;

#define B_ 4
#define N_ 2048
#define IN_F 512
#define OUT_F 512
#define INTERNAL 256
#define REL_DIM 10
#define NUM_REL 6
#define ALPHA_ 0.2f
#define NEG_INF_ -9000000000000000.0f
#define EPS_LN_ 1e-5f

#define LAMBDA_INIT_ 0.35550906759096927f
#define ONE_MINUS_LAMBDA_ 0.64449093240903073f

// ---------------------------------------------------------------------------
// Device scratch
// ---------------------------------------------------------------------------
__device__ __align__(128) float g_Wh[(size_t)B_ * N_ * OUT_F];         // 16 MB
__device__ __align__(128) float g_hprime[(size_t)B_ * N_ * OUT_F];     // 16 MB
__device__ __align__(128) float g_att_fallback[(size_t)B_ * N_ * N_];  // 64 MB
__device__ float g_lpos[B_ * N_];
__device__ float g_rpos[B_ * N_];
__device__ float g_lneg[B_ * N_];
__device__ float g_rneg[B_ * N_];
__device__ float g_relp[NUM_REL];
__device__ float g_reln[NUM_REL];
__device__ float g_lam;

// ---------------------------------------------------------------------------
// Prep: lambda scalar + rel LUT
// ---------------------------------------------------------------------------
__global__ void prep_kernel(const float* __restrict__ ll1, const float* __restrict__ lr1,
                            const float* __restrict__ ll2, const float* __restrict__ lr2,
                            const float* __restrict__ rel_table,
                            const float* __restrict__ a_rel_pos,
                            const float* __restrict__ a_rel_neg) {
    __shared__ float s1[256];
    __shared__ float s2[256];
    int t = threadIdx.x;
    s1[t] = ll1[t] * lr1[t];
    s2[t] = ll2[t] * lr2[t];
    __syncthreads();
    for (int s = 128; s > 0; s >>= 1) {
        if (t < s) { s1[t] += s1[t + s]; s2[t] += s2[t + s]; }
        __syncthreads();
    }
    if (t == 0) g_lam = expf(s1[0]) - expf(s2[0]) + LAMBDA_INIT_;
    if (t < NUM_REL) {
        float sp = 0.f, sn = 0.f;
        #pragma unroll
        for (int d = 0; d < REL_DIM; d++) {
            float r = rel_table[t * REL_DIM + d];
            sp += r * a_rel_pos[d];
            sn += r * a_rel_neg[d];
        }
        g_relp[t] = sp;
        g_reln[t] = sn;
    }
}

// ---------------------------------------------------------------------------
// WMMA bf16 3x-split GEMM.  C = Ah*Bh + Ah*Bl + Al*Bh (fp32 accum).
// CTA tile 128x256, BK=32, 256 threads = 8 warps (2 in M x 4 in N),
// warp tile 64x64 = 4x4 fragments of 16x16x16. Double-buffered SMEM.
// grid: (N/256, M/128, batch)
// ---------------------------------------------------------------------------
#define BM 128
#define BN 256
#define BK 32
#define LDA 40    // bf16 elems per A smem row (32 + 8 pad)
#define LDB 264   // bf16 elems per B smem row (256 + 8 pad)

#define A_TILE_ELEMS (BM * LDA)              // 5120
#define B_TILE_ELEMS (BK * LDB)              // 8448
#define STAGE_ELEMS (2 * A_TILE_ELEMS + 2 * B_TILE_ELEMS)
#define GEMM_SMEM_BYTES (2 * STAGE_ELEMS * 2)

extern __shared__ __nv_bfloat16 g_smem_bf[];

__global__ __launch_bounds__(256, 1) void gemm_wmma_kernel(
    const float* __restrict__ A, const float* __restrict__ B, float* __restrict__ C,
    int K, int NN,
    size_t sA, size_t sB, size_t sC) {
    const int tid = threadIdx.x;
    const int wid = tid >> 5;
    const int wm = wid & 1;        // 0..1 (M, 64 rows each)
    const int wn = wid >> 1;       // 0..3 (N, 64 cols each)

    const int n0 = blockIdx.x * BN;
    const int m0 = blockIdx.y * BM;
    const int bz = blockIdx.z;

    const float* Ag = A + (size_t)bz * sA + (size_t)m0 * K;
    const float* Bg = B + (size_t)bz * sB;
    float*       Cg = C + (size_t)bz * sC;

    // per-thread gmem load coordinates
    const int ar = tid >> 3;           // A row base 0..31 (+32*i)
    const int ac4 = (tid & 7) * 4;     // A col (float)
    const int br = tid >> 6;           // B row base 0..3 (+4*i)
    const int bc4 = (tid & 63) * 4;    // B col

    wmma::fragment<wmma::accumulator, 16, 16, 16, float> acc[4][4];
    #pragma unroll
    for (int i = 0; i < 4; i++)
        #pragma unroll
        for (int j = 0; j < 4; j++) wmma::fill_fragment(acc[i][j], 0.0f);

    const int nt = K / BK;
    float4 av[4], bv[8];

    // prefetch tile 0
    #pragma unroll
    for (int i = 0; i < 4; i++)
        av[i] = *reinterpret_cast<const float4*>(Ag + (size_t)(ar + 32 * i) * K + ac4);
    #pragma unroll
    for (int i = 0; i < 8; i++)
        bv[i] = *reinterpret_cast<const float4*>(Bg + (size_t)(br + 4 * i) * NN + n0 + bc4);

    for (int t = 0; t < nt; t++) {
        const int p = t & 1;
        __nv_bfloat16* sa_hi = g_smem_bf + p * STAGE_ELEMS;
        __nv_bfloat16* sa_lo = sa_hi + A_TILE_ELEMS;
        __nv_bfloat16* sb_hi = sa_lo + A_TILE_ELEMS;
        __nv_bfloat16* sb_lo = sb_hi + B_TILE_ELEMS;

        #pragma unroll
        for (int i = 0; i < 4; i++) {
            const float* v = reinterpret_cast<const float*>(&av[i]);
            __nv_bfloat16 h0 = __float2bfloat16_rn(v[0]);
            __nv_bfloat16 h1 = __float2bfloat16_rn(v[1]);
            __nv_bfloat16 h2 = __float2bfloat16_rn(v[2]);
            __nv_bfloat16 h3 = __float2bfloat16_rn(v[3]);
            __nv_bfloat16 l0 = __float2bfloat16_rn(v[0] - __bfloat162float(h0));
            __nv_bfloat16 l1 = __float2bfloat16_rn(v[1] - __bfloat162float(h1));
            __nv_bfloat16 l2 = __float2bfloat16_rn(v[2] - __bfloat162float(h2));
            __nv_bfloat16 l3 = __float2bfloat16_rn(v[3] - __bfloat162float(h3));
            int off = (ar + 32 * i) * LDA + ac4;
            *reinterpret_cast<__nv_bfloat162*>(sa_hi + off)     = __nv_bfloat162(h0, h1);
            *reinterpret_cast<__nv_bfloat162*>(sa_hi + off + 2) = __nv_bfloat162(h2, h3);
            *reinterpret_cast<__nv_bfloat162*>(sa_lo + off)     = __nv_bfloat162(l0, l1);
            *reinterpret_cast<__nv_bfloat162*>(sa_lo + off + 2) = __nv_bfloat162(l2, l3);
        }
        #pragma unroll
        for (int i = 0; i < 8; i++) {
            const float* v = reinterpret_cast<const float*>(&bv[i]);
            __nv_bfloat16 h0 = __float2bfloat16_rn(v[0]);
            __nv_bfloat16 h1 = __float2bfloat16_rn(v[1]);
            __nv_bfloat16 h2 = __float2bfloat16_rn(v[2]);
            __nv_bfloat16 h3 = __float2bfloat16_rn(v[3]);
            __nv_bfloat16 l0 = __float2bfloat16_rn(v[0] - __bfloat162float(h0));
            __nv_bfloat16 l1 = __float2bfloat16_rn(v[1] - __bfloat162float(h1));
            __nv_bfloat16 l2 = __float2bfloat16_rn(v[2] - __bfloat162float(h2));
            __nv_bfloat16 l3 = __float2bfloat16_rn(v[3] - __bfloat162float(h3));
            int off = (br + 4 * i) * LDB + bc4;
            *reinterpret_cast<__nv_bfloat162*>(sb_hi + off)     = __nv_bfloat162(h0, h1);
            *reinterpret_cast<__nv_bfloat162*>(sb_hi + off + 2) = __nv_bfloat162(h2, h3);
            *reinterpret_cast<__nv_bfloat162*>(sb_lo + off)     = __nv_bfloat162(l0, l1);
            *reinterpret_cast<__nv_bfloat162*>(sb_lo + off + 2) = __nv_bfloat162(l2, l3);
        }
        __syncthreads();

        if (t + 1 < nt) {
            const int k0 = (t + 1) * BK;
            #pragma unroll
            for (int i = 0; i < 4; i++)
                av[i] = *reinterpret_cast<const float4*>(Ag + (size_t)(ar + 32 * i) * K + k0 + ac4);
            #pragma unroll
            for (int i = 0; i < 8; i++)
                bv[i] = *reinterpret_cast<const float4*>(Bg + (size_t)(k0 + br + 4 * i) * NN + n0 + bc4);
        }

        #pragma unroll
        for (int kk = 0; kk < BK; kk += 16) {
            wmma::fragment<wmma::matrix_a, 16, 16, 16, __nv_bfloat16, wmma::row_major> ah[4], al[4];
            #pragma unroll
            for (int i = 0; i < 4; i++) {
                int row = wm * 64 + i * 16;
                wmma::load_matrix_sync(ah[i], sa_hi + row * LDA + kk, LDA);
                wmma::load_matrix_sync(al[i], sa_lo + row * LDA + kk, LDA);
            }
            #pragma unroll
            for (int j = 0; j < 4; j++) {
                wmma::fragment<wmma::matrix_b, 16, 16, 16, __nv_bfloat16, wmma::row_major> bh, bl;
                int col = wn * 64 + j * 16;
                wmma::load_matrix_sync(bh, sb_hi + kk * LDB + col, LDB);
                wmma::load_matrix_sync(bl, sb_lo + kk * LDB + col, LDB);
                #pragma unroll
                for (int i = 0; i < 4; i++) {
                    wmma::mma_sync(acc[i][j], ah[i], bh, acc[i][j]);
                    wmma::mma_sync(acc[i][j], ah[i], bl, acc[i][j]);
                    wmma::mma_sync(acc[i][j], al[i], bh, acc[i][j]);
                }
            }
        }
        __syncthreads();
    }

    #pragma unroll
    for (int i = 0; i < 4; i++) {
        int row = m0 + wm * 64 + i * 16;
        #pragma unroll
        for (int j = 0; j < 4; j++) {
            int col = n0 + wn * 64 + j * 16;
            wmma::store_matrix_sync(Cg + (size_t)row * NN + col, acc[i][j], NN,
                                    wmma::mem_row_major);
        }
    }
}

// ---------------------------------------------------------------------------
// Per-row dots
// ---------------------------------------------------------------------------
__global__ void rowdots_kernel(const float* __restrict__ alp, const float* __restrict__ arp,
                               const float* __restrict__ aln, const float* __restrict__ arn) {
    int row = blockIdx.x;
    int t = threadIdx.x;
    const float* wh = g_Wh + (size_t)row * OUT_F;
    float whp = wh[t];
    float whn = wh[INTERNAL + t];
    __shared__ float s[4][256];
    s[0][t] = whp * alp[t];
    s[1][t] = whp * arp[t];
    s[2][t] = whn * aln[t];
    s[3][t] = whn * arn[t];
    __syncthreads();
    for (int st = 128; st > 0; st >>= 1) {
        if (t < st) {
            s[0][t] += s[0][t + st];
            s[1][t] += s[1][t + st];
            s[2][t] += s[2][t + st];
            s[3][t] += s[3][t + st];
        }
        __syncthreads();
    }
    if (t == 0) {
        g_lpos[row] = s[0][0];
        g_rpos[row] = s[1][0];
        g_lneg[row] = s[2][0];
        g_rneg[row] = s[3][0];
    }
}

// ---------------------------------------------------------------------------
// Attention rows: register-resident dual masked softmax + combine.
// 256 threads/row, each owns 8 contiguous j. Shuffle+smem block reductions.
// ---------------------------------------------------------------------------
__global__ __launch_bounds__(256) void attention_kernel(const int* __restrict__ adj,
                                                        float* __restrict__ att_out) {
    const int row = blockIdx.x;
    const int b = row >> 11;
    const int t = threadIdx.x;
    const int lane = t & 31;
    const int wrp = t >> 5;

    const float lp = g_lpos[row];
    const float ln_ = g_lneg[row];
    const float lam = g_lam;

    const int4* arow4 = reinterpret_cast<const int4*>(adj + (size_t)row * N_);
    const float4* rp4 = reinterpret_cast<const float4*>(g_rpos + b * N_);
    const float4* rn4 = reinterpret_cast<const float4*>(g_rneg + b * N_);

    int aj[8];
    {
        int4 a0 = arow4[t * 2];
        int4 a1 = arow4[t * 2 + 1];
        aj[0] = a0.x; aj[1] = a0.y; aj[2] = a0.z; aj[3] = a0.w;
        aj[4] = a1.x; aj[5] = a1.y; aj[6] = a1.z; aj[7] = a1.w;
    }
    float rpv[8], rnv[8];
    {
        float4 r0 = rp4[t * 2], r1 = rp4[t * 2 + 1];
        rpv[0] = r0.x; rpv[1] = r0.y; rpv[2] = r0.z; rpv[3] = r0.w;
        rpv[4] = r1.x; rpv[5] = r1.y; rpv[6] = r1.z; rpv[7] = r1.w;
        float4 s0 = rn4[t * 2], s1 = rn4[t * 2 + 1];
        rnv[0] = s0.x; rnv[1] = s0.y; rnv[2] = s0.z; rnv[3] = s0.w;
        rnv[4] = s1.x; rnv[5] = s1.y; rnv[6] = s1.z; rnv[7] = s1.w;
    }

    float ep[8], en[8];
    float mp = -INFINITY, mn = -INFINITY;
    #pragma unroll
    for (int i = 0; i < 8; i++) {
        int a = aj[i];
        if (a > 0) {
            float x = lp + rpv[i] + g_relp[a];
            ep[i] = (x >= 0.f) ? x : ALPHA_ * x;
            float y = ln_ + rnv[i] + g_reln[a];
            en[i] = (y >= 0.f) ? y : ALPHA_ * y;
        } else {
            ep[i] = NEG_INF_;
            en[i] = NEG_INF_;
        }
        mp = fmaxf(mp, ep[i]);
        mn = fmaxf(mn, en[i]);
    }

    __shared__ float sm[2][8];
    // warp max
    #pragma unroll
    for (int o = 16; o > 0; o >>= 1) {
        mp = fmaxf(mp, __shfl_xor_sync(0xFFFFFFFFu, mp, o));
        mn = fmaxf(mn, __shfl_xor_sync(0xFFFFFFFFu, mn, o));
    }
    if (lane == 0) { sm[0][wrp] = mp; sm[1][wrp] = mn; }
    __syncthreads();
    {
        float a = sm[0][lane & 7], c = sm[1][lane & 7];
        #pragma unroll
        for (int o = 4; o > 0; o >>= 1) {
            a = fmaxf(a, __shfl_xor_sync(0xFFFFFFFFu, a, o));
            c = fmaxf(c, __shfl_xor_sync(0xFFFFFFFFu, c, o));
        }
        mp = a; mn = c;
    }

    float sp = 0.f, sn = 0.f;
    #pragma unroll
    for (int i = 0; i < 8; i++) {
        ep[i] = __expf(ep[i] - mp);
        en[i] = __expf(en[i] - mn);
        sp += ep[i];
        sn += en[i];
    }
    #pragma unroll
    for (int o = 16; o > 0; o >>= 1) {
        sp += __shfl_xor_sync(0xFFFFFFFFu, sp, o);
        sn += __shfl_xor_sync(0xFFFFFFFFu, sn, o);
    }
    __syncthreads();
    if (lane == 0) { sm[0][wrp] = sp; sm[1][wrp] = sn; }
    __syncthreads();
    {
        float a = sm[0][lane & 7], c = sm[1][lane & 7];
        #pragma unroll
        for (int o = 4; o > 0; o >>= 1) {
            a += __shfl_xor_sync(0xFFFFFFFFu, a, o);
            c += __shfl_xor_sync(0xFFFFFFFFu, c, o);
        }
        sp = a; sn = c;
    }

    const float isp = 1.0f / sp;
    const float isn = lam / sn;
    float4* orow4 = reinterpret_cast<float4*>(att_out + (size_t)row * N_);
    float4 o0 = make_float4(ep[0] * isp - en[0] * isn, ep[1] * isp - en[1] * isn,
                            ep[2] * isp - en[2] * isn, ep[3] * isp - en[3] * isn);
    float4 o1 = make_float4(ep[4] * isp - en[4] * isn, ep[5] * isp - en[5] * isn,
                            ep[6] * isp - en[6] * isn, ep[7] * isp - en[7] * isn);
    orow4[t * 2] = o0;
    orow4[t * 2 + 1] = o1;
}

// ---------------------------------------------------------------------------
// LayerNorm + scale + exact GELU
// ---------------------------------------------------------------------------
__global__ void ln_gelu_kernel(const float* __restrict__ gamma, const float* __restrict__ beta,
                               float* __restrict__ out) {
    int row = blockIdx.x;
    int t = threadIdx.x;
    const float* x = g_hprime + (size_t)row * OUT_F;
    float x0 = x[t];
    float x1 = x[t + 256];
    __shared__ float red[256];
    red[t] = x0 + x1; __syncthreads();
    for (int s = 128; s > 0; s >>= 1) { if (t < s) red[t] += red[t + s]; __syncthreads(); }
    float mu = red[0] * (1.0f / OUT_F);
    __syncthreads();
    float d0 = x0 - mu, d1 = x1 - mu;
    red[t] = d0 * d0 + d1 * d1; __syncthreads();
    for (int s = 128; s > 0; s >>= 1) { if (t < s) red[t] += red[t + s]; __syncthreads(); }
    float var = red[0] * (1.0f / OUT_F);
    float inv = rsqrtf(var + EPS_LN_);

    float y0 = (d0 * inv * gamma[t] + beta[t]) * ONE_MINUS_LAMBDA_;
    float y1 = (d1 * inv * gamma[t + 256] + beta[t + 256]) * ONE_MINUS_LAMBDA_;
    float* o = out + (size_t)row * OUT_F;
    o[t]       = y0 * 0.5f * (1.0f + erff(y0 * 0.7071067811865476f));
    o[t + 256] = y1 * 0.5f * (1.0f + erff(y1 * 0.7071067811865476f));
}

// ---------------------------------------------------------------------------
// Launch
// ---------------------------------------------------------------------------
extern "C" void kernel_launch(void* const* d_in, const int* in_sizes, int n_in,
                              void* d_out, int out_size) {
    const float* h         = (const float*)d_in[0];
    const int*   adj       = (const int*)d_in[1];
    const float* W         = (const float*)d_in[2];
    const float* alp       = (const float*)d_in[3];
    const float* arp       = (const float*)d_in[4];
    const float* aln       = (const float*)d_in[5];
    const float* arn       = (const float*)d_in[6];
    const float* rel_table = (const float*)d_in[7];
    const float* a_rel_pos = (const float*)d_in[8];
    const float* a_rel_neg = (const float*)d_in[9];
    const float* ll1       = (const float*)d_in[10];
    const float* lr1       = (const float*)d_in[11];
    const float* ll2       = (const float*)d_in[12];
    const float* lr2       = (const float*)d_in[13];
    const float* gamma     = (const float*)d_in[14];
    const float* beta      = (const float*)d_in[15];
    float* out = (float*)d_out;

    const size_t GE = (size_t)B_ * N_ * OUT_F;
    const size_t AT = (size_t)B_ * N_ * N_;

    float* att_out;
    if ((size_t)out_size >= GE + AT) {
        att_out = out + GE;
    } else {
        void* p;
        cudaGetSymbolAddress(&p, g_att_fallback);
        att_out = (float*)p;
    }

    void *pWh, *pHp;
    cudaGetSymbolAddress(&pWh, g_Wh);
    cudaGetSymbolAddress(&pHp, g_hprime);

    cudaFuncSetAttribute(gemm_wmma_kernel, cudaFuncAttributeMaxDynamicSharedMemorySize,
                         GEMM_SMEM_BYTES);

    // 1) scalars + rel LUT
    prep_kernel<<<1, 256>>>(ll1, lr1, ll2, lr2, rel_table, a_rel_pos, a_rel_neg);

    // 2) Wh = h @ W   (M=8192, N=512, K=512)
    {
        dim3 grid(OUT_F / BN, (B_ * N_) / BM, 1);
        gemm_wmma_kernel<<<grid, 256, GEMM_SMEM_BYTES>>>(h, W, (float*)pWh, IN_F, OUT_F, 0, 0, 0);
    }

    // 3) per-row scores
    rowdots_kernel<<<B_ * N_, 256>>>(alp, arp, aln, arn);

    // 4) attention rows
    attention_kernel<<<B_ * N_, 256>>>(adj, att_out);

    // 5) h_prime = attention @ Wh   (per batch M=2048, N=512, K=2048)
    {
        dim3 grid(OUT_F / BN, N_ / BM, B_);
        gemm_wmma_kernel<<<grid, 256, GEMM_SMEM_BYTES>>>(att_out, (const float*)pWh, (float*)pHp,
                                                         N_, OUT_F,
                                                         (size_t)N_ * N_, (size_t)N_ * OUT_F,
                                                         (size_t)N_ * OUT_F);
    }

    // 6) LN + GELU
    ln_gelu_kernel<<<B_ * N_, 256>>>(gamma, beta, out);
}

// round 5
// speedup vs baseline: 2.1527x; 1.0460x over previous
#include <cuda_runtime.h>
#include <cuda_bf16.h>
#include <mma.h>
#include <math.h>
#include <stdint.h>

using namespace nvcuda;

#define B_ 4
#define N_ 2048
#define IN_F 512
#define OUT_F 512
#define INTERNAL 256
#define REL_DIM 10
#define NUM_REL 6
#define ALPHA_ 0.2f
#define NEG_INF_ -9000000000000000.0f
#define EPS_LN_ 1e-5f

#define LAMBDA_INIT_ 0.35550906759096927f
#define ONE_MINUS_LAMBDA_ 0.64449093240903073f

// ---------------------------------------------------------------------------
// Device scratch
// ---------------------------------------------------------------------------
__device__ __align__(128) float g_Wh[(size_t)B_ * N_ * OUT_F];            // 16 MB
__device__ __align__(128) float g_hprime[(size_t)B_ * N_ * OUT_F];        // 16 MB
__device__ __align__(128) float g_att_fallback[(size_t)B_ * N_ * N_];     // 64 MB
__device__ __align__(128) __nv_bfloat16 g_h_hi[(size_t)B_ * N_ * IN_F];   // 8.4 MB
__device__ __align__(128) __nv_bfloat16 g_h_lo[(size_t)B_ * N_ * IN_F];
__device__ __align__(128) __nv_bfloat16 g_W_hi[(size_t)IN_F * OUT_F];
__device__ __align__(128) __nv_bfloat16 g_W_lo[(size_t)IN_F * OUT_F];
__device__ __align__(128) __nv_bfloat16 g_Wh_hi[(size_t)B_ * N_ * OUT_F];
__device__ __align__(128) __nv_bfloat16 g_Wh_lo[(size_t)B_ * N_ * OUT_F];
__device__ __align__(128) __nv_bfloat16 g_att_hi[(size_t)B_ * N_ * N_];   // 33.5 MB
__device__ __align__(128) __nv_bfloat16 g_att_lo[(size_t)B_ * N_ * N_];
__device__ float g_lpos[B_ * N_];
__device__ float g_rpos[B_ * N_];
__device__ float g_lneg[B_ * N_];
__device__ float g_rneg[B_ * N_];
__device__ float g_relp[NUM_REL];
__device__ float g_reln[NUM_REL];
__device__ float g_lam;

// ---------------------------------------------------------------------------
// cp.async helpers
// ---------------------------------------------------------------------------
__device__ __forceinline__ uint32_t smem_u32(const void* p) {
    uint32_t a;
    asm("{ .reg .u64 t; cvta.to.shared.u64 t, %1; cvt.u32.u64 %0, t; }" : "=r"(a) : "l"(p));
    return a;
}
__device__ __forceinline__ void cp_async16(uint32_t s, const void* g) {
    asm volatile("cp.async.cg.shared.global [%0], [%1], 16;" :: "r"(s), "l"(g));
}
#define CP_COMMIT() asm volatile("cp.async.commit_group;" ::: "memory")
#define CP_WAIT(n) asm volatile("cp.async.wait_group %0;" :: "n"(n) : "memory")

// ---------------------------------------------------------------------------
// Prep: lambda scalar + rel LUT
// ---------------------------------------------------------------------------
__global__ void prep_kernel(const float* __restrict__ ll1, const float* __restrict__ lr1,
                            const float* __restrict__ ll2, const float* __restrict__ lr2,
                            const float* __restrict__ rel_table,
                            const float* __restrict__ a_rel_pos,
                            const float* __restrict__ a_rel_neg) {
    __shared__ float s1[256];
    __shared__ float s2[256];
    int t = threadIdx.x;
    s1[t] = ll1[t] * lr1[t];
    s2[t] = ll2[t] * lr2[t];
    __syncthreads();
    for (int s = 128; s > 0; s >>= 1) {
        if (t < s) { s1[t] += s1[t + s]; s2[t] += s2[t + s]; }
        __syncthreads();
    }
    if (t == 0) g_lam = expf(s1[0]) - expf(s2[0]) + LAMBDA_INIT_;
    if (t < NUM_REL) {
        float sp = 0.f, sn = 0.f;
        #pragma unroll
        for (int d = 0; d < REL_DIM; d++) {
            float r = rel_table[t * REL_DIM + d];
            sp += r * a_rel_pos[d];
            sn += r * a_rel_neg[d];
        }
        g_relp[t] = sp;
        g_reln[t] = sn;
    }
}

// ---------------------------------------------------------------------------
// fp32 -> bf16 hi/lo split (vectorized, grid-stride)
// ---------------------------------------------------------------------------
__global__ void split_kernel(const float* __restrict__ in, __nv_bfloat16* __restrict__ hi,
                             __nv_bfloat16* __restrict__ lo, size_t n4) {
    size_t i = blockIdx.x * (size_t)blockDim.x + threadIdx.x;
    if (i >= n4) return;
    float4 v = reinterpret_cast<const float4*>(in)[i];
    __nv_bfloat16 h0 = __float2bfloat16_rn(v.x);
    __nv_bfloat16 h1 = __float2bfloat16_rn(v.y);
    __nv_bfloat16 h2 = __float2bfloat16_rn(v.z);
    __nv_bfloat16 h3 = __float2bfloat16_rn(v.w);
    __nv_bfloat162 hp0(h0, h1), hp1(h2, h3);
    __nv_bfloat162 lp0(__float2bfloat16_rn(v.x - __bfloat162float(h0)),
                       __float2bfloat16_rn(v.y - __bfloat162float(h1)));
    __nv_bfloat162 lp1(__float2bfloat16_rn(v.z - __bfloat162float(h2)),
                       __float2bfloat16_rn(v.w - __bfloat162float(h3)));
    uint2 hv = make_uint2(*reinterpret_cast<uint32_t*>(&hp0), *reinterpret_cast<uint32_t*>(&hp1));
    uint2 lv = make_uint2(*reinterpret_cast<uint32_t*>(&lp0), *reinterpret_cast<uint32_t*>(&lp1));
    reinterpret_cast<uint2*>(hi)[i] = hv;
    reinterpret_cast<uint2*>(lo)[i] = lv;
}

// ---------------------------------------------------------------------------
// Pure-bf16 3x-split WMMA GEMM with cp.async double buffering.
//   C[M,N] (fp32) = (Ah+Al)[M,K] @ (Bh+Bl)[K,N], 3 terms: AhBh + AhBl + AlBh
// CTA tile 128x256, BK=32, 8 warps (2M x 4N), warp tile 64x64.
// ---------------------------------------------------------------------------
#define BM 128
#define BN 256
#define BK 32
#define LDA 40
#define LDB 264
#define A_TILE_ELEMS (BM * LDA)                 // 5120
#define B_TILE_ELEMS (BK * LDB)                 // 8448
#define STAGE_ELEMS (2 * A_TILE_ELEMS + 2 * B_TILE_ELEMS)  // 27136
#define GEMM_SMEM_BYTES (2 * STAGE_ELEMS * 2)   // 108544

extern __shared__ __nv_bfloat16 g_smem_bf[];

__global__ __launch_bounds__(256, 1) void gemm_bf16_kernel(
    const __nv_bfloat16* __restrict__ Ah, const __nv_bfloat16* __restrict__ Al,
    const __nv_bfloat16* __restrict__ Bh, const __nv_bfloat16* __restrict__ Bl,
    float* __restrict__ C, int K, int NN,
    size_t sA, size_t sB, size_t sC) {
    const int tid = threadIdx.x;
    const int wid = tid >> 5;
    const int wm = wid & 1;
    const int wn = wid >> 1;

    const int n0 = blockIdx.x * BN;
    const int m0 = blockIdx.y * BM;
    const int bz = blockIdx.z;

    const __nv_bfloat16* Ahg = Ah + (size_t)bz * sA + (size_t)m0 * K;
    const __nv_bfloat16* Alg = Al + (size_t)bz * sA + (size_t)m0 * K;
    const __nv_bfloat16* Bhg = Bh + (size_t)bz * sB + n0;
    const __nv_bfloat16* Blg = Bl + (size_t)bz * sB + n0;
    float* Cg = C + (size_t)bz * sC;

    const uint32_t smem_base = smem_u32(g_smem_bf);

    // copy coordinates
    const int a_row = tid >> 1;        // 0..127 (2 chunks per row: tid&1 -> c 0/1 then +2)
    const int a_c0 = (tid & 1) * 2;    // chunk col 0 or 2 (each chunk = 8 bf16 = 16B)
    const int b_row = tid >> 5;        // 0..7 (+8,16,24)
    const int b_c = tid & 31;          // 0..31

    auto cp_stage = [&](int t, int p) {
        const int k0 = t * BK;
        uint32_t st = smem_base + p * STAGE_ELEMS * 2;
        uint32_t sa_hi = st;
        uint32_t sa_lo = st + A_TILE_ELEMS * 2;
        uint32_t sb_hi = st + 2 * A_TILE_ELEMS * 2;
        uint32_t sb_lo = st + 2 * A_TILE_ELEMS * 2 + B_TILE_ELEMS * 2;
        // A: 128 rows x 32 bf16 (4 chunks of 8) per plane
        #pragma unroll
        for (int i = 0; i < 2; i++) {
            int c = a_c0 + i;
            size_t go = (size_t)a_row * K + k0 + c * 8;
            uint32_t so = (uint32_t)(a_row * LDA + c * 8) * 2;
            cp_async16(sa_hi + so, Ahg + go);
            cp_async16(sa_lo + so, Alg + go);
        }
        // B: 32 rows x 256 bf16 (32 chunks of 8) per plane
        #pragma unroll
        for (int i = 0; i < 4; i++) {
            int row = b_row + i * 8;
            size_t go = (size_t)(k0 + row) * NN + b_c * 8;
            uint32_t so = (uint32_t)(row * LDB + b_c * 8) * 2;
            cp_async16(sb_hi + so, Bhg + go);
            cp_async16(sb_lo + so, Blg + go);
        }
    };

    wmma::fragment<wmma::accumulator, 16, 16, 16, float> acc[4][4];
    #pragma unroll
    for (int i = 0; i < 4; i++)
        #pragma unroll
        for (int j = 0; j < 4; j++) wmma::fill_fragment(acc[i][j], 0.0f);

    const int nt = K / BK;
    cp_stage(0, 0);
    CP_COMMIT();

    for (int t = 0; t < nt; t++) {
        const int p = t & 1;
        if (t + 1 < nt) {
            cp_stage(t + 1, p ^ 1);
            CP_COMMIT();
            CP_WAIT(1);
        } else {
            CP_WAIT(0);
        }
        __syncthreads();

        __nv_bfloat16* sa_hi = g_smem_bf + p * STAGE_ELEMS;
        __nv_bfloat16* sa_lo = sa_hi + A_TILE_ELEMS;
        __nv_bfloat16* sb_hi = sa_lo + A_TILE_ELEMS;
        __nv_bfloat16* sb_lo = sb_hi + B_TILE_ELEMS;

        #pragma unroll
        for (int kk = 0; kk < BK; kk += 16) {
            wmma::fragment<wmma::matrix_a, 16, 16, 16, __nv_bfloat16, wmma::row_major> ah[4], al[4];
            #pragma unroll
            for (int i = 0; i < 4; i++) {
                int row = wm * 64 + i * 16;
                wmma::load_matrix_sync(ah[i], sa_hi + row * LDA + kk, LDA);
                wmma::load_matrix_sync(al[i], sa_lo + row * LDA + kk, LDA);
            }
            #pragma unroll
            for (int j = 0; j < 4; j++) {
                wmma::fragment<wmma::matrix_b, 16, 16, 16, __nv_bfloat16, wmma::row_major> bh, bl;
                int col = wn * 64 + j * 16;
                wmma::load_matrix_sync(bh, sb_hi + kk * LDB + col, LDB);
                wmma::load_matrix_sync(bl, sb_lo + kk * LDB + col, LDB);
                #pragma unroll
                for (int i = 0; i < 4; i++) {
                    wmma::mma_sync(acc[i][j], ah[i], bh, acc[i][j]);
                    wmma::mma_sync(acc[i][j], ah[i], bl, acc[i][j]);
                    wmma::mma_sync(acc[i][j], al[i], bh, acc[i][j]);
                }
            }
        }
        __syncthreads();
    }

    #pragma unroll
    for (int i = 0; i < 4; i++) {
        int row = m0 + wm * 64 + i * 16;
        #pragma unroll
        for (int j = 0; j < 4; j++) {
            int col = n0 + wn * 64 + j * 16;
            wmma::store_matrix_sync(Cg + (size_t)row * NN + col, acc[i][j], NN,
                                    wmma::mem_row_major);
        }
    }
}

// ---------------------------------------------------------------------------
// Per-row dots
// ---------------------------------------------------------------------------
__global__ void rowdots_kernel(const float* __restrict__ alp, const float* __restrict__ arp,
                               const float* __restrict__ aln, const float* __restrict__ arn) {
    int row = blockIdx.x;
    int t = threadIdx.x;
    const float* wh = g_Wh + (size_t)row * OUT_F;
    float whp = wh[t];
    float whn = wh[INTERNAL + t];
    __shared__ float s[4][256];
    s[0][t] = whp * alp[t];
    s[1][t] = whp * arp[t];
    s[2][t] = whn * aln[t];
    s[3][t] = whn * arn[t];
    __syncthreads();
    for (int st = 128; st > 0; st >>= 1) {
        if (t < st) {
            s[0][t] += s[0][t + st];
            s[1][t] += s[1][t + st];
            s[2][t] += s[2][t + st];
            s[3][t] += s[3][t + st];
        }
        __syncthreads();
    }
    if (t == 0) {
        g_lpos[row] = s[0][0];
        g_rpos[row] = s[1][0];
        g_lneg[row] = s[2][0];
        g_rneg[row] = s[3][0];
    }
}

// ---------------------------------------------------------------------------
// Attention rows: register-resident dual masked softmax + combine.
// Writes fp32 att (output) + bf16 hi/lo planes (GEMM2 operands).
// ---------------------------------------------------------------------------
__global__ __launch_bounds__(256) void attention_kernel(const int* __restrict__ adj,
                                                        float* __restrict__ att_out) {
    const int row = blockIdx.x;
    const int b = row >> 11;
    const int t = threadIdx.x;
    const int lane = t & 31;
    const int wrp = t >> 5;

    const float lp = g_lpos[row];
    const float ln_ = g_lneg[row];
    const float lam = g_lam;

    const int4* arow4 = reinterpret_cast<const int4*>(adj + (size_t)row * N_);
    const float4* rp4 = reinterpret_cast<const float4*>(g_rpos + b * N_);
    const float4* rn4 = reinterpret_cast<const float4*>(g_rneg + b * N_);

    int aj[8];
    {
        int4 a0 = arow4[t * 2];
        int4 a1 = arow4[t * 2 + 1];
        aj[0] = a0.x; aj[1] = a0.y; aj[2] = a0.z; aj[3] = a0.w;
        aj[4] = a1.x; aj[5] = a1.y; aj[6] = a1.z; aj[7] = a1.w;
    }
    float rpv[8], rnv[8];
    {
        float4 r0 = rp4[t * 2], r1 = rp4[t * 2 + 1];
        rpv[0] = r0.x; rpv[1] = r0.y; rpv[2] = r0.z; rpv[3] = r0.w;
        rpv[4] = r1.x; rpv[5] = r1.y; rpv[6] = r1.z; rpv[7] = r1.w;
        float4 s0 = rn4[t * 2], s1 = rn4[t * 2 + 1];
        rnv[0] = s0.x; rnv[1] = s0.y; rnv[2] = s0.z; rnv[3] = s0.w;
        rnv[4] = s1.x; rnv[5] = s1.y; rnv[6] = s1.z; rnv[7] = s1.w;
    }

    float ep[8], en[8];
    float mp = -INFINITY, mn = -INFINITY;
    #pragma unroll
    for (int i = 0; i < 8; i++) {
        int a = aj[i];
        if (a > 0) {
            float x = lp + rpv[i] + g_relp[a];
            ep[i] = (x >= 0.f) ? x : ALPHA_ * x;
            float y = ln_ + rnv[i] + g_reln[a];
            en[i] = (y >= 0.f) ? y : ALPHA_ * y;
        } else {
            ep[i] = NEG_INF_;
            en[i] = NEG_INF_;
        }
        mp = fmaxf(mp, ep[i]);
        mn = fmaxf(mn, en[i]);
    }

    __shared__ float sm[2][8];
    #pragma unroll
    for (int o = 16; o > 0; o >>= 1) {
        mp = fmaxf(mp, __shfl_xor_sync(0xFFFFFFFFu, mp, o));
        mn = fmaxf(mn, __shfl_xor_sync(0xFFFFFFFFu, mn, o));
    }
    if (lane == 0) { sm[0][wrp] = mp; sm[1][wrp] = mn; }
    __syncthreads();
    {
        float a = sm[0][lane & 7], c = sm[1][lane & 7];
        #pragma unroll
        for (int o = 4; o > 0; o >>= 1) {
            a = fmaxf(a, __shfl_xor_sync(0xFFFFFFFFu, a, o));
            c = fmaxf(c, __shfl_xor_sync(0xFFFFFFFFu, c, o));
        }
        mp = a; mn = c;
    }

    float sp = 0.f, sn = 0.f;
    #pragma unroll
    for (int i = 0; i < 8; i++) {
        ep[i] = __expf(ep[i] - mp);
        en[i] = __expf(en[i] - mn);
        sp += ep[i];
        sn += en[i];
    }
    #pragma unroll
    for (int o = 16; o > 0; o >>= 1) {
        sp += __shfl_xor_sync(0xFFFFFFFFu, sp, o);
        sn += __shfl_xor_sync(0xFFFFFFFFu, sn, o);
    }
    __syncthreads();
    if (lane == 0) { sm[0][wrp] = sp; sm[1][wrp] = sn; }
    __syncthreads();
    {
        float a = sm[0][lane & 7], c = sm[1][lane & 7];
        #pragma unroll
        for (int o = 4; o > 0; o >>= 1) {
            a += __shfl_xor_sync(0xFFFFFFFFu, a, o);
            c += __shfl_xor_sync(0xFFFFFFFFu, c, o);
        }
        sp = a; sn = c;
    }

    const float isp = 1.0f / sp;
    const float isn = lam / sn;
    float ov[8];
    #pragma unroll
    for (int i = 0; i < 8; i++) ov[i] = ep[i] * isp - en[i] * isn;

    const size_t base = (size_t)row * N_;
    float4* orow4 = reinterpret_cast<float4*>(att_out + base);
    orow4[t * 2]     = make_float4(ov[0], ov[1], ov[2], ov[3]);
    orow4[t * 2 + 1] = make_float4(ov[4], ov[5], ov[6], ov[7]);

    // bf16 hi/lo planes
    __nv_bfloat162 hv[4], lv[4];
    #pragma unroll
    for (int i = 0; i < 4; i++) {
        __nv_bfloat16 h0 = __float2bfloat16_rn(ov[i * 2]);
        __nv_bfloat16 h1 = __float2bfloat16_rn(ov[i * 2 + 1]);
        hv[i] = __nv_bfloat162(h0, h1);
        lv[i] = __nv_bfloat162(__float2bfloat16_rn(ov[i * 2] - __bfloat162float(h0)),
                               __float2bfloat16_rn(ov[i * 2 + 1] - __bfloat162float(h1)));
    }
    reinterpret_cast<uint4*>(g_att_hi + base)[t] = *reinterpret_cast<uint4*>(hv);
    reinterpret_cast<uint4*>(g_att_lo + base)[t] = *reinterpret_cast<uint4*>(lv);
}

// ---------------------------------------------------------------------------
// LayerNorm + scale + exact GELU
// ---------------------------------------------------------------------------
__global__ void ln_gelu_kernel(const float* __restrict__ gamma, const float* __restrict__ beta,
                               float* __restrict__ out) {
    int row = blockIdx.x;
    int t = threadIdx.x;
    const float* x = g_hprime + (size_t)row * OUT_F;
    float x0 = x[t];
    float x1 = x[t + 256];
    __shared__ float red[256];
    red[t] = x0 + x1; __syncthreads();
    for (int s = 128; s > 0; s >>= 1) { if (t < s) red[t] += red[t + s]; __syncthreads(); }
    float mu = red[0] * (1.0f / OUT_F);
    __syncthreads();
    float d0 = x0 - mu, d1 = x1 - mu;
    red[t] = d0 * d0 + d1 * d1; __syncthreads();
    for (int s = 128; s > 0; s >>= 1) { if (t < s) red[t] += red[t + s]; __syncthreads(); }
    float var = red[0] * (1.0f / OUT_F);
    float inv = rsqrtf(var + EPS_LN_);

    float y0 = (d0 * inv * gamma[t] + beta[t]) * ONE_MINUS_LAMBDA_;
    float y1 = (d1 * inv * gamma[t + 256] + beta[t + 256]) * ONE_MINUS_LAMBDA_;
    float* o = out + (size_t)row * OUT_F;
    o[t]       = y0 * 0.5f * (1.0f + erff(y0 * 0.7071067811865476f));
    o[t + 256] = y1 * 0.5f * (1.0f + erff(y1 * 0.7071067811865476f));
}

// ---------------------------------------------------------------------------
// Launch
// ---------------------------------------------------------------------------
extern "C" void kernel_launch(void* const* d_in, const int* in_sizes, int n_in,
                              void* d_out, int out_size) {
    const float* h         = (const float*)d_in[0];
    const int*   adj       = (const int*)d_in[1];
    const float* W         = (const float*)d_in[2];
    const float* alp       = (const float*)d_in[3];
    const float* arp       = (const float*)d_in[4];
    const float* aln       = (const float*)d_in[5];
    const float* arn       = (const float*)d_in[6];
    const float* rel_table = (const float*)d_in[7];
    const float* a_rel_pos = (const float*)d_in[8];
    const float* a_rel_neg = (const float*)d_in[9];
    const float* ll1       = (const float*)d_in[10];
    const float* lr1       = (const float*)d_in[11];
    const float* ll2       = (const float*)d_in[12];
    const float* lr2       = (const float*)d_in[13];
    const float* gamma     = (const float*)d_in[14];
    const float* beta      = (const float*)d_in[15];
    float* out = (float*)d_out;

    const size_t GE = (size_t)B_ * N_ * OUT_F;
    const size_t AT = (size_t)B_ * N_ * N_;

    float* att_out;
    if ((size_t)out_size >= GE + AT) {
        att_out = out + GE;
    } else {
        void* p;
        cudaGetSymbolAddress(&p, g_att_fallback);
        att_out = (float*)p;
    }

    void *pWh, *pHp, *p_h_hi, *p_h_lo, *p_W_hi, *p_W_lo, *p_Wh_hi, *p_Wh_lo, *p_att_hi, *p_att_lo;
    cudaGetSymbolAddress(&pWh, g_Wh);
    cudaGetSymbolAddress(&pHp, g_hprime);
    cudaGetSymbolAddress(&p_h_hi, g_h_hi);
    cudaGetSymbolAddress(&p_h_lo, g_h_lo);
    cudaGetSymbolAddress(&p_W_hi, g_W_hi);
    cudaGetSymbolAddress(&p_W_lo, g_W_lo);
    cudaGetSymbolAddress(&p_Wh_hi, g_Wh_hi);
    cudaGetSymbolAddress(&p_Wh_lo, g_Wh_lo);
    cudaGetSymbolAddress(&p_att_hi, g_att_hi);
    cudaGetSymbolAddress(&p_att_lo, g_att_lo);

    cudaFuncSetAttribute(gemm_bf16_kernel, cudaFuncAttributeMaxDynamicSharedMemorySize,
                         GEMM_SMEM_BYTES);

    // 1) scalars + rel LUT
    prep_kernel<<<1, 256>>>(ll1, lr1, ll2, lr2, rel_table, a_rel_pos, a_rel_neg);

    // 2) split h and W to bf16 hi/lo
    {
        size_t n4 = (size_t)B_ * N_ * IN_F / 4;
        split_kernel<<<(unsigned)((n4 + 255) / 256), 256>>>(h, (__nv_bfloat16*)p_h_hi,
                                                            (__nv_bfloat16*)p_h_lo, n4);
        size_t w4 = (size_t)IN_F * OUT_F / 4;
        split_kernel<<<(unsigned)((w4 + 255) / 256), 256>>>(W, (__nv_bfloat16*)p_W_hi,
                                                            (__nv_bfloat16*)p_W_lo, w4);
    }

    // 3) Wh = h @ W   (M=8192, N=512, K=512)
    {
        dim3 grid(OUT_F / BN, (B_ * N_) / BM, 1);
        gemm_bf16_kernel<<<grid, 256, GEMM_SMEM_BYTES>>>(
            (const __nv_bfloat16*)p_h_hi, (const __nv_bfloat16*)p_h_lo,
            (const __nv_bfloat16*)p_W_hi, (const __nv_bfloat16*)p_W_lo,
            (float*)pWh, IN_F, OUT_F, 0, 0, 0);
    }

    // 4) split Wh
    {
        size_t n4 = (size_t)B_ * N_ * OUT_F / 4;
        split_kernel<<<(unsigned)((n4 + 255) / 256), 256>>>((const float*)pWh,
                                                            (__nv_bfloat16*)p_Wh_hi,
                                                            (__nv_bfloat16*)p_Wh_lo, n4);
    }

    // 5) per-row scores
    rowdots_kernel<<<B_ * N_, 256>>>(alp, arp, aln, arn);

    // 6) attention rows (fp32 out + bf16 hi/lo planes)
    attention_kernel<<<B_ * N_, 256>>>(adj, att_out);

    // 7) h_prime = attention @ Wh   (per batch M=2048, N=512, K=2048)
    {
        dim3 grid(OUT_F / BN, N_ / BM, B_);
        gemm_bf16_kernel<<<grid, 256, GEMM_SMEM_BYTES>>>(
            (const __nv_bfloat16*)p_att_hi, (const __nv_bfloat16*)p_att_lo,
            (const __nv_bfloat16*)p_Wh_hi, (const __nv_bfloat16*)p_Wh_lo,
            (float*)pHp, N_, OUT_F,
            (size_t)N_ * N_, (size_t)N_ * OUT_F, (size_t)N_ * OUT_F);
    }

    // 8) LN + GELU
    ln_gelu_kernel<<<B_ * N_, 256>>>(gamma, beta, out);
}